// round 9
// baseline (speedup 1.0000x reference)
#include <cuda_runtime.h>
#include <math.h>

#define Bb   16
#define Tt   512
#define Pdim 1024
#define Ddim 2048
#define G4   8192      // 4*D
#define LNEPS 1e-3f

#define NCTA 128       // persistent-scan grid (must all be co-resident; <= 148 SMs)
#define NTHR 256

// smem layout (floats) for scan kernel
#define SM_SS     0        // phase B: S^T staged [2048][16] = 32768
#define SM_HS     0        // phase A: H staged [16][1024] = 16384 (union with SS)
#define SM_GRED   16384    // phase A: partials [4][16][64] = 4096
#define SM_PWS    32768    // phase B: Pw slice [2048][8] = 16384
#define SM_HPART  49152    // phase B: partials [16][16][8] = 2048
#define SM_FLOATS 51200
#define SM_BYTES  (SM_FLOATS * 4)

// ---------------- scratch (static device globals; no allocation) -------------
__device__ float g_XG[(size_t)Bb * Tt * G4];        // 256 MB: pre-activations
__device__ float g_BUF[3][(size_t)Bb * Tt * Pdim];  // 3 x 32 MB ping-pong
__device__ float g_ST[Ddim * Bb];                   // s transposed [d][b]
__device__ float g_C[Bb * Ddim];                    // cell state
__device__ float g_H[Bb * Pdim];                    // hidden state

// grid barrier state
__device__ unsigned g_cnt = 0;
__device__ volatile unsigned g_gen = 0;

__device__ __forceinline__ float sigm(float x) { return 1.0f / (1.0f + expf(-x)); }

// ---------------- packed f32x2 helpers (Blackwell) ---------------------------
__device__ __forceinline__ unsigned long long fma2(unsigned long long a,
                                                   unsigned long long b,
                                                   unsigned long long c) {
    unsigned long long d;
    asm("fma.rn.f32x2 %0, %1, %2, %3;" : "=l"(d) : "l"(a), "l"(b), "l"(c));
    return d;
}
__device__ __forceinline__ unsigned long long pack2(float lo, float hi) {
    unsigned long long r;
    asm("mov.b64 %0, {%1, %2};" : "=l"(r) : "f"(lo), "f"(hi));
    return r;
}
__device__ __forceinline__ float2 unpack2(unsigned long long v) {
    float2 r;
    asm("mov.b64 {%0, %1}, %2;" : "=f"(r.x), "=f"(r.y) : "l"(v));
    return r;
}

// ---------------- software grid barrier --------------------------------------
__device__ __forceinline__ void grid_sync() {
    __syncthreads();
    if (threadIdx.x == 0) {
        __threadfence();
        unsigned gen = g_gen;
        if (atomicAdd(&g_cnt, 1u) == (unsigned)(gridDim.x - 1)) {
            g_cnt = 0;
            __threadfence();
            g_gen = gen + 1;
        } else {
            while (g_gen == gen) { __nanosleep(32); }
        }
        __threadfence();
    }
    __syncthreads();
}

// ---------------- init states ------------------------------------------------
__global__ void k_init(const float* __restrict__ state) {
    int i = blockIdx.x * blockDim.x + threadIdx.x;
    if (i < Bb * Ddim) g_C[i] = state[i];
    if (i < Bb * Pdim) {
        int b = i / Pdim, p = i % Pdim;
        g_H[i] = state[Bb * Ddim + b * Ddim + p];
    }
}

// ---------------- big GEMM: C[M,N] = A @ W + bias (128x128x8, f32x2) --------
// convmode==1: row r of A starts at ((r/511)*512 + r%511)*1024 and spans 2048
__global__ void __launch_bounds__(NTHR) k_gemm(const float* __restrict__ A,
                                               const float* __restrict__ W,
                                               const float* __restrict__ bias,
                                               float* __restrict__ C,
                                               int M, int N, int K, int convmode) {
    __shared__ float As[8][128];
    __shared__ float Bs[8][128];

    int tid = threadIdx.x;
    int tx = tid & 15, ty = tid >> 4;
    int m0 = blockIdx.y * 128, n0 = blockIdx.x * 128;

    unsigned long long acc[8][4];
#pragma unroll
    for (int i = 0; i < 8; i++)
#pragma unroll
        for (int j = 0; j < 4; j++) acc[i][j] = 0ull;

    int arow = tid >> 1, ac4 = (tid & 1) * 4;
    int brow = tid >> 5, bc4 = (tid & 31) * 4;
    int r = m0 + arow;
    bool rok = (r < M);
    size_t abase = 0;
    if (rok) abase = convmode ? ((size_t)((r / 511) * 512 + (r % 511))) * (size_t)Pdim
                              : (size_t)r * (size_t)K;

    for (int k0 = 0; k0 < K; k0 += 8) {
        float4 av = rok ? *(const float4*)(A + abase + k0 + ac4)
                        : make_float4(0.f, 0.f, 0.f, 0.f);
        As[ac4 + 0][arow] = av.x; As[ac4 + 1][arow] = av.y;
        As[ac4 + 2][arow] = av.z; As[ac4 + 3][arow] = av.w;
        *(float4*)&Bs[brow][bc4] =
            *(const float4*)(W + (size_t)(k0 + brow) * (size_t)N + n0 + bc4);
        __syncthreads();
#pragma unroll
        for (int kk = 0; kk < 8; kk++) {
            float4 a0 = *(const float4*)&As[kk][ty * 8];
            float4 a1 = *(const float4*)&As[kk][ty * 8 + 4];
            ulonglong2 b0 = *(const ulonglong2*)&Bs[kk][tx * 8];
            ulonglong2 b1 = *(const ulonglong2*)&Bs[kk][tx * 8 + 4];
            float aa[8] = {a0.x, a0.y, a0.z, a0.w, a1.x, a1.y, a1.z, a1.w};
#pragma unroll
            for (int i = 0; i < 8; i++) {
                unsigned long long ap = pack2(aa[i], aa[i]);
                acc[i][0] = fma2(ap, b0.x, acc[i][0]);
                acc[i][1] = fma2(ap, b0.y, acc[i][1]);
                acc[i][2] = fma2(ap, b1.x, acc[i][2]);
                acc[i][3] = fma2(ap, b1.y, acc[i][3]);
            }
        }
        __syncthreads();
    }
#pragma unroll
    for (int i = 0; i < 8; i++) {
        int rr = m0 + ty * 8 + i;
        if (rr < M) {
            float* cp = C + (size_t)rr * (size_t)N + n0 + tx * 8;
            const float* bp = bias + n0 + tx * 8;
#pragma unroll
            for (int jj = 0; jj < 4; jj++) {
                float2 v = unpack2(acc[i][jj]);
                cp[jj * 2 + 0] = v.x + bp[jj * 2 + 0];
                cp[jj * 2 + 1] = v.y + bp[jj * 2 + 1];
            }
        }
    }
}

// ---------------- persistent scan: whole-layer LSTM recurrence ---------------
// 128 CTAs x 256 thr, all co-resident. CTA owns d-slice [cta*16, cta*16+16)
// for gates/cell, and p-slice [cta*8, cta*8+8) for the projection output.
// c[b][d] lives in one register per thread for the whole scan.
__global__ void __launch_bounds__(NTHR, 1) k_scan(const float* __restrict__ Wh,
                                                  const float* __restrict__ Pw,
                                                  const float* __restrict__ XG,
                                                  float* __restrict__ RAW,
                                                  int T) {
    extern __shared__ float sm[];
    float* Hs    = sm + SM_HS;
    float* Gred  = sm + SM_GRED;
    float* Ss    = sm + SM_SS;
    float* Pws   = sm + SM_PWS;
    float* Hpart = sm + SM_HPART;

    const int tid = threadIdx.x;
    const int cta = blockIdx.x;
    const int d0 = cta * 16;   // gate d-slice
    const int p0 = cta * 8;    // proj col-slice

    // phase A compute mapping
    const int q  = tid >> 6;          // k-quarter (256 each)
    const int rr = tid & 63;
    const int bq = rr >> 4;           // batch quad (4 b's)
    const int cq = rr & 15;           // col quad within 64 local cols
    const int gate = cq >> 2;
    const int j4 = (cq & 3) << 2;
    const float* wbase = Wh + (size_t)(q * 256) * G4 + (size_t)gate * Ddim + d0 + j4;

    // gate/cell mapping: one (b, dl) tuple per thread
    const int gb = tid >> 4;
    const int dl = tid & 15;
    float c_reg = g_C[gb * Ddim + d0 + dl];

    // phase B mapping
    const int b2 = tid & 15;
    const int ks = tid >> 4;          // 16 k-splits of 128

    for (int t = 0; t < T; t++) {
        // ---- stage H into smem ----
#pragma unroll 4
        for (int i = tid; i < (Bb * Pdim) / 4; i += NTHR)
            ((float4*)Hs)[i] = ((const float4*)g_H)[i];
        __syncthreads();

        // ---- phase A: partial G = H @ Wh over this thread's k-quarter ----
        {
            unsigned long long acc[4][2];
#pragma unroll
            for (int i = 0; i < 4; i++) { acc[i][0] = 0ull; acc[i][1] = 0ull; }
            const float* hrow = Hs + (bq * 4) * Pdim + q * 256;
            const float* wp = wbase;
#pragma unroll 1
            for (int k = 0; k < 256; k += 4) {
                ulonglong2 wv[4];
#pragma unroll
                for (int u = 0; u < 4; u++)
                    wv[u] = *(const ulonglong2*)(wp + (size_t)(k + u) * G4);
#pragma unroll
                for (int u = 0; u < 4; u++) {
#pragma unroll
                    for (int i = 0; i < 4; i++) {
                        float a = hrow[i * Pdim + k + u];
                        unsigned long long ap = pack2(a, a);
                        acc[i][0] = fma2(ap, wv[u].x, acc[i][0]);
                        acc[i][1] = fma2(ap, wv[u].y, acc[i][1]);
                    }
                }
            }
#pragma unroll
            for (int i = 0; i < 4; i++) {
                float2 v0 = unpack2(acc[i][0]);
                float2 v1 = unpack2(acc[i][1]);
                float* gp = Gred + q * 1024 + (bq * 4 + i) * 64 + cq * 4;
                gp[0] = v0.x; gp[1] = v0.y; gp[2] = v1.x; gp[3] = v1.y;
            }
        }
        __syncthreads();

        // ---- gates + cell update (fused, no extra barrier) ----
        {
            const float* xg = XG + ((size_t)gb * T + t) * (size_t)G4 + d0 + dl;
            float gv[4];
#pragma unroll
            for (int g = 0; g < 4; g++) {
                float s = Gred[0 * 1024 + gb * 64 + g * 16 + dl]
                        + Gred[1 * 1024 + gb * 64 + g * 16 + dl]
                        + Gred[2 * 1024 + gb * 64 + g * 16 + dl]
                        + Gred[3 * 1024 + gb * 64 + g * 16 + dl];
                gv[g] = s + xg[(size_t)g * Ddim];
            }
            float cc = sigm(gv[2] + 1.0f) * c_reg + sigm(gv[0]) * tanhf(gv[1]);
            c_reg = cc;
            float sv = sigm(gv[3]) * tanhf(cc);
            g_ST[(size_t)(d0 + dl) * Bb + gb] = sv;
        }

        grid_sync();

        // ---- phase B: H = S @ proj for this CTA's 8 output cols ----
        // stage S^T (full, 128 KB) and Pw slice (64 KB) into smem
#pragma unroll 4
        for (int i = tid; i < (Ddim * Bb) / 4; i += NTHR)
            ((float4*)Ss)[i] = ((const float4*)g_ST)[i];
        {
            const float* pwb = Pw + p0;
#pragma unroll 4
            for (int e = tid; e < 4096; e += NTHR) {
                int k = e >> 1, hf = (e & 1) * 4;
                *(float4*)&Pws[k * 8 + hf] =
                    *(const float4*)(pwb + (size_t)k * Pdim + hf);
            }
        }
        __syncthreads();
        {
            unsigned long long acc[4] = {0ull, 0ull, 0ull, 0ull};
            const float* ssb = Ss + ks * 128 * Bb + b2;
            const float* pwk = Pws + ks * 128 * 8;
#pragma unroll 4
            for (int k = 0; k < 128; k++) {
                float s = ssb[k * Bb];
                unsigned long long sp = pack2(s, s);
                ulonglong2 w0 = *(const ulonglong2*)(pwk + k * 8);
                ulonglong2 w1 = *(const ulonglong2*)(pwk + k * 8 + 4);
                acc[0] = fma2(sp, w0.x, acc[0]);
                acc[1] = fma2(sp, w0.y, acc[1]);
                acc[2] = fma2(sp, w1.x, acc[2]);
                acc[3] = fma2(sp, w1.y, acc[3]);
            }
            float* hp = Hpart + (ks * 16 + b2) * 8;
#pragma unroll
            for (int jj = 0; jj < 4; jj++) {
                float2 v = unpack2(acc[jj]);
                hp[jj * 2 + 0] = v.x;
                hp[jj * 2 + 1] = v.y;
            }
        }
        __syncthreads();
        if (tid < 128) {
            int b = tid >> 3, col = tid & 7;
            float h = 0.0f;
#pragma unroll
            for (int k2 = 0; k2 < 16; k2++)
                h += Hpart[(k2 * 16 + b) * 8 + col];
            g_H[b * Pdim + p0 + col] = h;
            RAW[((size_t)b * T + t) * (size_t)Pdim + p0 + col] = h;
        }

        grid_sync();
    }

    // write back final cell state
    g_C[gb * Ddim + d0 + dl] = c_reg;
}

// ---------------- layernorm over last dim (1024) ----------------------------
__global__ void k_ln(const float* __restrict__ X, float* __restrict__ Y,
                     const float* __restrict__ gamma, const float* __restrict__ beta) {
    __shared__ float red[256];
    int row = blockIdx.x;
    const float* x = X + (size_t)row * Pdim;
    float* y = Y + (size_t)row * Pdim;
    int tid = threadIdx.x;

    float s = 0.0f;
    for (int i = tid; i < Pdim; i += 256) s += x[i];
    red[tid] = s; __syncthreads();
    for (int o = 128; o > 0; o >>= 1) {
        if (tid < o) red[tid] += red[tid + o];
        __syncthreads();
    }
    float mean = red[0] * (1.0f / Pdim);
    __syncthreads();

    float v = 0.0f;
    for (int i = tid; i < Pdim; i += 256) { float d = x[i] - mean; v += d * d; }
    red[tid] = v; __syncthreads();
    for (int o = 128; o > 0; o >>= 1) {
        if (tid < o) red[tid] += red[tid + o];
        __syncthreads();
    }
    float rstd = rsqrtf(red[0] * (1.0f / Pdim) + LNEPS);
    __syncthreads();

    for (int i = tid; i < Pdim; i += 256)
        y[i] = (x[i] - mean) * rstd * gamma[i] + beta[i];
}

// ---------------- final c,h copy --------------------------------------------
__global__ void k_out_ch(float* __restrict__ oc, float* __restrict__ oh) {
    int idx = blockIdx.x * blockDim.x + threadIdx.x;
    if (idx < Bb * Ddim) oc[idx] = g_C[idx];
    if (idx < Bb * Pdim) oh[idx] = g_H[idx];
}

// ---------------- host driver -----------------------------------------------
extern "C" void kernel_launch(void* const* d_in, const int* in_sizes, int n_in,
                              void* d_out, int out_size) {
    const float* inputs  = (const float*)d_in[0];
    const float* state   = (const float*)d_in[1];
    const float* kernels = (const float*)d_in[2];
    const float* biases  = (const float*)d_in[3];
    const float* projs   = (const float*)d_in[4];
    const float* gamma   = (const float*)d_in[5];
    const float* beta    = (const float*)d_in[6];
    const float* convw   = (const float*)d_in[7];
    const float* convb   = (const float*)d_in[8];
    float* out = (float*)d_out;

    cudaFuncSetAttribute(k_scan, cudaFuncAttributeMaxDynamicSharedMemorySize,
                         SM_BYTES);

    float* BUF = nullptr;
    float* XG  = nullptr;
    cudaGetSymbolAddress((void**)&BUF, g_BUF);
    cudaGetSymbolAddress((void**)&XG, g_XG);
    const size_t BUFSZ = (size_t)Bb * Tt * Pdim;
    float* A  = BUF;
    float* Bu = BUF + BUFSZ;
    float* Cu = BUF + 2 * BUFSZ;

    k_init<<<(Bb * Ddim + 255) / 256, 256>>>(state);

    const float* cur = inputs;
    for (int l = 0; l < 4; l++) {
        int T = (l < 2) ? 512 : 511;
        int Mrows = Bb * T;
        const float* Wx = kernels + (size_t)l * 2 * Pdim * G4;
        const float* Wh = Wx + (size_t)Pdim * G4;
        const float* bi = biases + l * G4;
        const float* Pw = projs + (size_t)l * Ddim * Pdim;

        // pre-activations XG = cur @ Wx + bias
        dim3 gx(G4 / 128, (Mrows + 127) / 128);
        k_gemm<<<gx, NTHR>>>(cur, Wx, bi, XG, Mrows, G4, Pdim, 0);

        // whole-layer recurrence in ONE persistent launch
        k_scan<<<NCTA, NTHR, SM_BYTES>>>(Wh, Pw, XG, A, T);

        // layernorm
        float* LNout;
        if (l == 0)      LNout = Bu;
        else if (l == 1) LNout = Cu;
        else if (l == 2) LNout = Cu;
        else             LNout = out;
        k_ln<<<Mrows, 256>>>(A, LNout, gamma, beta);

        if (l == 1) {
            // temporal conv (window 2, VALID): GEMM with overlapped A rows
            int Mc = Bb * 511;
            dim3 gc(Pdim / 128, (Mc + 127) / 128);
            k_gemm<<<gc, NTHR>>>(Cu, convw, convb, Bu, Mc, Pdim, 2 * Pdim, 1);
            cur = Bu;
        } else if (l == 0) {
            cur = Bu;
        } else if (l == 2) {
            cur = Cu;
        }
    }

    // outputs: out [16,511,1024], then c [16,2048], then h [16,1024]
    size_t off_c = (size_t)Bb * 511 * Pdim;
    size_t off_h = off_c + (size_t)Bb * Ddim;
    k_out_ch<<<(Bb * Ddim + 255) / 256, 256>>>(out + off_c, out + off_h);
}

// round 10
// speedup vs baseline: 1.2015x; 1.2015x over previous
#include <cuda_runtime.h>
#include <math.h>

#define Bb   16
#define Tt   512
#define Pdim 1024
#define Ddim 2048
#define G4   8192      // 4*D
#define LNEPS 1e-3f

#define NCTA 128       // persistent-scan grid (must all be co-resident; <= 148 SMs)
#define NTHR 256

// smem layout (floats) for scan kernel
#define SM_HS     0        // phase A: H staged [16][1024] = 16384
#define SM_GRED   16384    // phase A: partials [8][16][64] = 8192
#define SM_SS     0        // phase B: S^T staged [2048][16] = 32768 (union with A)
#define SM_PWS    32768    // phase B: Pw slice [2048][8] = 16384
#define SM_HPART  49152    // phase B: partials [16][16][8] = 2048
#define SM_FLOATS 51200
#define SM_BYTES  (SM_FLOATS * 4)

// ---------------- scratch (static device globals; no allocation) -------------
__device__ float g_XG[(size_t)Bb * Tt * G4];        // 256 MB: pre-activations
__device__ float g_BUF[3][(size_t)Bb * Tt * Pdim];  // 3 x 32 MB ping-pong
__device__ float g_ST[Ddim * Bb];                   // s transposed [d][b]
__device__ float g_C[Bb * Ddim];                    // cell state
__device__ float g_H[Bb * Pdim];                    // hidden state

// grid barrier state
__device__ unsigned g_cnt = 0;
__device__ volatile unsigned g_gen = 0;

__device__ __forceinline__ float sigm(float x) { return 1.0f / (1.0f + expf(-x)); }

// ---------------- packed f32x2 helpers (Blackwell) ---------------------------
__device__ __forceinline__ unsigned long long fma2(unsigned long long a,
                                                   unsigned long long b,
                                                   unsigned long long c) {
    unsigned long long d;
    asm("fma.rn.f32x2 %0, %1, %2, %3;" : "=l"(d) : "l"(a), "l"(b), "l"(c));
    return d;
}
__device__ __forceinline__ unsigned long long pack2(float lo, float hi) {
    unsigned long long r;
    asm("mov.b64 %0, {%1, %2};" : "=l"(r) : "f"(lo), "f"(hi));
    return r;
}
__device__ __forceinline__ float2 unpack2(unsigned long long v) {
    float2 r;
    asm("mov.b64 {%0, %1}, %2;" : "=f"(r.x), "=f"(r.y) : "l"(v));
    return r;
}

// ---------------- software grid barrier --------------------------------------
__device__ __forceinline__ void grid_sync() {
    __syncthreads();
    if (threadIdx.x == 0) {
        __threadfence();
        unsigned gen = g_gen;
        if (atomicAdd(&g_cnt, 1u) == (unsigned)(gridDim.x - 1)) {
            g_cnt = 0;
            __threadfence();
            g_gen = gen + 1;
        } else {
            while (g_gen == gen) { __nanosleep(32); }
        }
        __threadfence();
    }
    __syncthreads();
}

// ---------------- init states ------------------------------------------------
__global__ void k_init(const float* __restrict__ state) {
    int i = blockIdx.x * blockDim.x + threadIdx.x;
    if (i < Bb * Ddim) g_C[i] = state[i];
    if (i < Bb * Pdim) {
        int b = i / Pdim, p = i % Pdim;
        g_H[i] = state[Bb * Ddim + b * Ddim + p];
    }
}

// ---------------- big GEMM: C[M,N] = A @ W + bias ---------------------------
// 128x128x16 tiles, double-buffered smem, one sync per k-tile, 2 CTAs/SM.
// convmode==1: row r of A starts at ((r/511)*512 + r%511)*1024, spans 2048.
__global__ void __launch_bounds__(NTHR, 2) k_gemm(const float* __restrict__ A,
                                                  const float* __restrict__ W,
                                                  const float* __restrict__ bias,
                                                  float* __restrict__ C,
                                                  int M, int N, int K, int convmode) {
    __shared__ float As[2][16][132];
    __shared__ float Bs[2][16][128];

    int tid = threadIdx.x;
    int tx = tid & 15, ty = tid >> 4;
    int m0 = blockIdx.y * 128, n0 = blockIdx.x * 128;

    int ar = tid >> 1, ac = (tid & 1) * 8;      // A tile: 128 rows x 16 k
    int br = tid >> 4, bc = (tid & 15) * 8;     // B tile: 16 k x 128 n
    int r = m0 + ar;
    bool rok = (r < M);
    size_t abase = 0;
    if (rok) abase = convmode ? ((size_t)((r / 511) * 512 + (r % 511))) * (size_t)Pdim
                              : (size_t)r * (size_t)K;

    unsigned long long acc[8][4];
#pragma unroll
    for (int i = 0; i < 8; i++)
#pragma unroll
        for (int j = 0; j < 4; j++) acc[i][j] = 0ull;

    // prologue: tile 0 -> buf 0
    {
        float4 a0 = make_float4(0.f, 0.f, 0.f, 0.f), a1 = a0;
        if (rok) {
            a0 = *(const float4*)(A + abase + ac);
            a1 = *(const float4*)(A + abase + ac + 4);
        }
        float4 b0v = *(const float4*)(W + (size_t)br * N + n0 + bc);
        float4 b1v = *(const float4*)(W + (size_t)br * N + n0 + bc + 4);
#pragma unroll
        for (int j = 0; j < 4; j++) {
            As[0][ac + j][ar]     = (&a0.x)[j];
            As[0][ac + 4 + j][ar] = (&a1.x)[j];
        }
        *(float4*)&Bs[0][br][bc]     = b0v;
        *(float4*)&Bs[0][br][bc + 4] = b1v;
    }
    __syncthreads();

    int buf = 0;
    for (int k0 = 0; k0 < K; k0 += 16) {
        bool more = (k0 + 16) < K;
        float4 na0 = make_float4(0.f, 0.f, 0.f, 0.f), na1 = na0, nb0, nb1;
        if (more) {
            if (rok) {
                na0 = *(const float4*)(A + abase + k0 + 16 + ac);
                na1 = *(const float4*)(A + abase + k0 + 16 + ac + 4);
            }
            nb0 = *(const float4*)(W + (size_t)(k0 + 16 + br) * N + n0 + bc);
            nb1 = *(const float4*)(W + (size_t)(k0 + 16 + br) * N + n0 + bc + 4);
        }
#pragma unroll
        for (int kk = 0; kk < 16; kk++) {
            float4 av0 = *(const float4*)&As[buf][kk][ty * 8];
            float4 av1 = *(const float4*)&As[buf][kk][ty * 8 + 4];
            ulonglong2 bb0 = *(const ulonglong2*)&Bs[buf][kk][tx * 8];
            ulonglong2 bb1 = *(const ulonglong2*)&Bs[buf][kk][tx * 8 + 4];
            float aa[8] = {av0.x, av0.y, av0.z, av0.w, av1.x, av1.y, av1.z, av1.w};
#pragma unroll
            for (int i = 0; i < 8; i++) {
                unsigned long long ap = pack2(aa[i], aa[i]);
                acc[i][0] = fma2(ap, bb0.x, acc[i][0]);
                acc[i][1] = fma2(ap, bb0.y, acc[i][1]);
                acc[i][2] = fma2(ap, bb1.x, acc[i][2]);
                acc[i][3] = fma2(ap, bb1.y, acc[i][3]);
            }
        }
        if (more) {
            int nb = buf ^ 1;
#pragma unroll
            for (int j = 0; j < 4; j++) {
                As[nb][ac + j][ar]     = (&na0.x)[j];
                As[nb][ac + 4 + j][ar] = (&na1.x)[j];
            }
            *(float4*)&Bs[nb][br][bc]     = nb0;
            *(float4*)&Bs[nb][br][bc + 4] = nb1;
        }
        __syncthreads();
        buf ^= 1;
    }

#pragma unroll
    for (int i = 0; i < 8; i++) {
        int rr = m0 + ty * 8 + i;
        if (rr < M) {
            float* cp = C + (size_t)rr * (size_t)N + n0 + tx * 8;
            const float* bp = bias + n0 + tx * 8;
#pragma unroll
            for (int jj = 0; jj < 4; jj++) {
                float2 v = unpack2(acc[i][jj]);
                cp[jj * 2 + 0] = v.x + bp[jj * 2 + 0];
                cp[jj * 2 + 1] = v.y + bp[jj * 2 + 1];
            }
        }
    }
}

// ---------------- persistent scan: whole-layer LSTM recurrence ---------------
// 128 CTAs x 256 thr, all co-resident. CTA owns d-slice [cta*16, cta*16+16)
// for gates/cell, and p-slice [cta*8, cta*8+8) for the projection output.
// Phase A: 8 k-slices x 2 b-halves x 16 col-quads -> each weight LDG.128
// feeds 8 batch rows (16 fma2 per LDG.128).
__global__ void __launch_bounds__(NTHR, 1) k_scan(const float* __restrict__ Wh,
                                                  const float* __restrict__ Pw,
                                                  const float* __restrict__ XG,
                                                  float* __restrict__ RAW,
                                                  int T) {
    extern __shared__ float sm[];
    float* Hs    = sm + SM_HS;
    float* Gred  = sm + SM_GRED;
    float* Ss    = sm + SM_SS;
    float* Pws   = sm + SM_PWS;
    float* Hpart = sm + SM_HPART;

    const int tid = threadIdx.x;
    const int cta = blockIdx.x;
    const int d0 = cta * 16;   // gate d-slice
    const int p0 = cta * 8;    // proj col-slice

    // phase A compute mapping
    const int ks8  = tid >> 5;         // k-slice of 128 (0..7) — constant per warp
    const int lane = tid & 31;
    const int bh   = lane >> 4;        // b-half (8 b's)
    const int cq   = lane & 15;        // col-quad (4 cols within 64)
    const int gate = cq >> 2;
    const int j4 = (cq & 3) << 2;
    const float* wbase = Wh + (size_t)(ks8 * 128) * G4 + (size_t)gate * Ddim + d0 + j4;

    // gate/cell mapping: one (b, dl) tuple per thread
    const int gb = tid >> 4;
    const int dl = tid & 15;
    float c_reg = g_C[gb * Ddim + d0 + dl];

    // phase B mapping
    const int b2 = tid & 15;
    const int ks = tid >> 4;          // 16 k-splits of 128

    for (int t = 0; t < T; t++) {
        // ---- stage H into smem ----
#pragma unroll 4
        for (int i = tid; i < (Bb * Pdim) / 4; i += NTHR)
            ((float4*)Hs)[i] = ((const float4*)g_H)[i];
        __syncthreads();

        // ---- phase A: partial G = H @ Wh over this thread's k-slice ----
        {
            unsigned long long acc[8][2];
#pragma unroll
            for (int i = 0; i < 8; i++) { acc[i][0] = 0ull; acc[i][1] = 0ull; }
            const float* hb = Hs + (bh * 8) * Pdim + ks8 * 128;
            const float* wp = wbase;
#pragma unroll 1
            for (int k = 0; k < 128; k += 4) {
                ulonglong2 wv[4];
#pragma unroll
                for (int u = 0; u < 4; u++)
                    wv[u] = *(const ulonglong2*)(wp + (size_t)(k + u) * G4);
                float4 hv[8];
#pragma unroll
                for (int b = 0; b < 8; b++)
                    hv[b] = *(const float4*)(hb + b * Pdim + k);
#pragma unroll
                for (int u = 0; u < 4; u++) {
#pragma unroll
                    for (int b = 0; b < 8; b++) {
                        float a = (&hv[b].x)[u];
                        unsigned long long ap = pack2(a, a);
                        acc[b][0] = fma2(ap, wv[u].x, acc[b][0]);
                        acc[b][1] = fma2(ap, wv[u].y, acc[b][1]);
                    }
                }
            }
#pragma unroll
            for (int b = 0; b < 8; b++) {
                float2 v0 = unpack2(acc[b][0]);
                float2 v1 = unpack2(acc[b][1]);
                float* gp = Gred + ks8 * 1024 + (bh * 8 + b) * 64 + cq * 4;
                gp[0] = v0.x; gp[1] = v0.y; gp[2] = v1.x; gp[3] = v1.y;
            }
        }
        __syncthreads();

        // ---- gates + cell update (fused) ----
        {
            const float* xg = XG + ((size_t)gb * T + t) * (size_t)G4 + d0 + dl;
            float gv[4];
#pragma unroll
            for (int g = 0; g < 4; g++) {
                float s = 0.0f;
#pragma unroll
                for (int sfrag = 0; sfrag < 8; sfrag++)
                    s += Gred[sfrag * 1024 + gb * 64 + g * 16 + dl];
                gv[g] = s + xg[(size_t)g * Ddim];
            }
            float cc = sigm(gv[2] + 1.0f) * c_reg + sigm(gv[0]) * tanhf(gv[1]);
            c_reg = cc;
            float sv = sigm(gv[3]) * tanhf(cc);
            g_ST[(size_t)(d0 + dl) * Bb + gb] = sv;
        }

        grid_sync();

        // ---- phase B: H = S @ proj for this CTA's 8 output cols ----
#pragma unroll 4
        for (int i = tid; i < (Ddim * Bb) / 4; i += NTHR)
            ((float4*)Ss)[i] = ((const float4*)g_ST)[i];
        {
            const float* pwb = Pw + p0;
#pragma unroll 4
            for (int e = tid; e < 4096; e += NTHR) {
                int k = e >> 1, hf = (e & 1) * 4;
                *(float4*)&Pws[k * 8 + hf] =
                    *(const float4*)(pwb + (size_t)k * Pdim + hf);
            }
        }
        __syncthreads();
        {
            unsigned long long acc[4] = {0ull, 0ull, 0ull, 0ull};
            const float* ssb = Ss + ks * 128 * Bb + b2;
            const float* pwk = Pws + ks * 128 * 8;
#pragma unroll 4
            for (int k = 0; k < 128; k++) {
                float s = ssb[k * Bb];
                unsigned long long sp = pack2(s, s);
                ulonglong2 w0 = *(const ulonglong2*)(pwk + k * 8);
                ulonglong2 w1 = *(const ulonglong2*)(pwk + k * 8 + 4);
                acc[0] = fma2(sp, w0.x, acc[0]);
                acc[1] = fma2(sp, w0.y, acc[1]);
                acc[2] = fma2(sp, w1.x, acc[2]);
                acc[3] = fma2(sp, w1.y, acc[3]);
            }
            float* hp = Hpart + (ks * 16 + b2) * 8;
#pragma unroll
            for (int jj = 0; jj < 4; jj++) {
                float2 v = unpack2(acc[jj]);
                hp[jj * 2 + 0] = v.x;
                hp[jj * 2 + 1] = v.y;
            }
        }
        __syncthreads();
        if (tid < 128) {
            int b = tid >> 3, col = tid & 7;
            float h = 0.0f;
#pragma unroll
            for (int k2 = 0; k2 < 16; k2++)
                h += Hpart[(k2 * 16 + b) * 8 + col];
            g_H[b * Pdim + p0 + col] = h;
            RAW[((size_t)b * T + t) * (size_t)Pdim + p0 + col] = h;
        }

        grid_sync();
    }

    // write back final cell state
    g_C[gb * Ddim + d0 + dl] = c_reg;
}

// ---------------- layernorm over last dim (1024) ----------------------------
__global__ void k_ln(const float* __restrict__ X, float* __restrict__ Y,
                     const float* __restrict__ gamma, const float* __restrict__ beta) {
    __shared__ float red[256];
    int row = blockIdx.x;
    const float* x = X + (size_t)row * Pdim;
    float* y = Y + (size_t)row * Pdim;
    int tid = threadIdx.x;

    float s = 0.0f;
    for (int i = tid; i < Pdim; i += 256) s += x[i];
    red[tid] = s; __syncthreads();
    for (int o = 128; o > 0; o >>= 1) {
        if (tid < o) red[tid] += red[tid + o];
        __syncthreads();
    }
    float mean = red[0] * (1.0f / Pdim);
    __syncthreads();

    float v = 0.0f;
    for (int i = tid; i < Pdim; i += 256) { float d = x[i] - mean; v += d * d; }
    red[tid] = v; __syncthreads();
    for (int o = 128; o > 0; o >>= 1) {
        if (tid < o) red[tid] += red[tid + o];
        __syncthreads();
    }
    float rstd = rsqrtf(red[0] * (1.0f / Pdim) + LNEPS);
    __syncthreads();

    for (int i = tid; i < Pdim; i += 256)
        y[i] = (x[i] - mean) * rstd * gamma[i] + beta[i];
}

// ---------------- final c,h copy --------------------------------------------
__global__ void k_out_ch(float* __restrict__ oc, float* __restrict__ oh) {
    int idx = blockIdx.x * blockDim.x + threadIdx.x;
    if (idx < Bb * Ddim) oc[idx] = g_C[idx];
    if (idx < Bb * Pdim) oh[idx] = g_H[idx];
}

// ---------------- host driver -----------------------------------------------
extern "C" void kernel_launch(void* const* d_in, const int* in_sizes, int n_in,
                              void* d_out, int out_size) {
    const float* inputs  = (const float*)d_in[0];
    const float* state   = (const float*)d_in[1];
    const float* kernels = (const float*)d_in[2];
    const float* biases  = (const float*)d_in[3];
    const float* projs   = (const float*)d_in[4];
    const float* gamma   = (const float*)d_in[5];
    const float* beta    = (const float*)d_in[6];
    const float* convw   = (const float*)d_in[7];
    const float* convb   = (const float*)d_in[8];
    float* out = (float*)d_out;

    cudaFuncSetAttribute(k_scan, cudaFuncAttributeMaxDynamicSharedMemorySize,
                         SM_BYTES);

    float* BUF = nullptr;
    float* XG  = nullptr;
    cudaGetSymbolAddress((void**)&BUF, g_BUF);
    cudaGetSymbolAddress((void**)&XG, g_XG);
    const size_t BUFSZ = (size_t)Bb * Tt * Pdim;
    float* A  = BUF;
    float* Bu = BUF + BUFSZ;
    float* Cu = BUF + 2 * BUFSZ;

    k_init<<<(Bb * Ddim + 255) / 256, 256>>>(state);

    const float* cur = inputs;
    for (int l = 0; l < 4; l++) {
        int T = (l < 2) ? 512 : 511;
        int Mrows = Bb * T;
        const float* Wx = kernels + (size_t)l * 2 * Pdim * G4;
        const float* Wh = Wx + (size_t)Pdim * G4;
        const float* bi = biases + l * G4;
        const float* Pw = projs + (size_t)l * Ddim * Pdim;

        // pre-activations XG = cur @ Wx + bias
        dim3 gx(G4 / 128, (Mrows + 127) / 128);
        k_gemm<<<gx, NTHR>>>(cur, Wx, bi, XG, Mrows, G4, Pdim, 0);

        // whole-layer recurrence in ONE persistent launch
        k_scan<<<NCTA, NTHR, SM_BYTES>>>(Wh, Pw, XG, A, T);

        // layernorm
        float* LNout;
        if (l == 0)      LNout = Bu;
        else if (l == 1) LNout = Cu;
        else if (l == 2) LNout = Cu;
        else             LNout = out;
        k_ln<<<Mrows, 256>>>(A, LNout, gamma, beta);

        if (l == 1) {
            // temporal conv (window 2, VALID): GEMM with overlapped A rows
            int Mc = Bb * 511;
            dim3 gc(Pdim / 128, (Mc + 127) / 128);
            k_gemm<<<gc, NTHR>>>(Cu, convw, convb, Bu, Mc, Pdim, 2 * Pdim, 1);
            cur = Bu;
        } else if (l == 0) {
            cur = Bu;
        } else if (l == 2) {
            cur = Cu;
        }
    }

    // outputs: out [16,511,1024], then c [16,2048], then h [16,1024]
    size_t off_c = (size_t)Bb * 511 * Pdim;
    size_t off_h = off_c + (size_t)Bb * Ddim;
    k_out_ch<<<(Bb * Ddim + 255) / 256, 256>>>(out + off_c, out + off_h);
}